// round 6
// baseline (speedup 1.0000x reference)
#include <cuda_runtime.h>
#include <cuda_bf16.h>

#define BB 512
#define TT 512
#define LL 64
#define GPB 4                       // batches per CTA
#define NCTA (BB / GPB)             // 128 CTAs, 1 per SM
#define NTHR (GPB * LL)             // 256 threads, 8 warps, 2 per SMSP

__device__ float g_res[BB];
__device__ unsigned int g_done = 0; // last-CTA ticket (self-resetting)

__global__ void __launch_bounds__(NTHR) crf_main_kernel(
    const float* __restrict__ emission,   // [B,T,L]
    const int*   __restrict__ target,     // [B,T]
    const float* __restrict__ mask,       // [B,T]
    const float* __restrict__ start_trans,// [L]
    const float* __restrict__ trans,      // [L,L]
    const float* __restrict__ end_trans,  // [L]
    float* __restrict__ out)
{
    __shared__ float2 sm_me[GPB][TT];               // (mask, endmask)
    __shared__ __align__(16) float sm_p[2][GPB][LL];
    __shared__ float sm_s0[2][GPB];
    __shared__ float sm_red[GPB][2];
    __shared__ float sm_fin[8];
    __shared__ unsigned int sm_last;

    const int tid  = threadIdx.x;
    const int g    = tid >> 6;          // local batch 0..3
    const int j    = tid & 63;          // label 0..63
    const int half = j >> 5;            // which warp within the 64-group
    const int lane = tid & 31;

    const int b = blockIdx.x * GPB + g;
    const float* emb  = emission + (size_t)b * TT * LL;
    const int*   tgt  = target   + (size_t)b * TT;
    const float* mrow = mask     + (size_t)b * TT;

    // stage (mask, end_mask) for this batch
    for (int t = j; t < TT; t += LL) {
        float m  = mrow[t];
        float nm = (t + 1 < TT) ? mrow[t + 1] : 0.0f;
        sm_me[g][t] = make_float2(m, (m > nm) ? 1.0f : 0.0f);
    }

    // E column j in registers: E[i][j] = exp(trans[i][j])
    float Ecol[LL];
    #pragma unroll
    for (int i = 0; i < LL; i++) Ecol[i] = __expf(trans[i * LL + j]);
    __syncthreads();

    // ---------------- path score: reduction over t (per batch) -------------
    float pacc = 0.0f;
    for (int t = 1 + j; t < TT; t += LL) {
        const int    tp = tgt[t - 1];
        const int    tc = tgt[t];
        const float2 me = sm_me[g][t];
        pacc += me.x * (trans[tp * LL + tc] + emb[(size_t)t * LL + tc])
              + me.y * end_trans[tc];
    }
    if (j == 0) {
        const int t0 = tgt[0];
        pacc += start_trans[t0] + emb[t0];
    }
    #pragma unroll
    for (int o = 16; o; o >>= 1) pacc += __shfl_xor_sync(0xffffffffu, pacc, o);
    if (lane == 0) sm_red[g][half] = pacc;
    __syncthreads();
    const float path_score = sm_red[g][0] + sm_red[g][1];

    // ---------------- forward recursion ----------------
    const float et = end_trans[j];
    float s = start_trans[j] + emb[j];          // t = 0

    if (j == 0) sm_s0[1][g] = s;
    __syncthreads();
    float S = sm_s0[1][g];                      // block-uniform lagged shift

    // emission prefetch, distance 2
    float em1 = emb[1 * LL + j];
    float em2 = emb[2 * LL + j];

    for (int t = 1; t < TT; t++) {
        const int   buf    = t & 1;
        const float em_cur = em1;
        em1 = em2;
        if (t + 2 < TT) em2 = emb[(size_t)(t + 2) * LL + j];

        if (j == 0) sm_s0[buf][g] = s;          // next iteration's shift
        sm_p[buf][g][j] = __expf(s - S);        // stabilized prob
        __syncthreads();                        // ONE barrier, all 4 batches

        // dot_j = sum_i p_i * E[i][j]  (64 FMA, 8 chains)
        const float4* p4 = (const float4*)sm_p[buf][g];
        float a0 = 0.f, a1 = 0.f, a2 = 0.f, a3 = 0.f;
        float a4 = 0.f, a5 = 0.f, a6 = 0.f, a7 = 0.f;
        #pragma unroll
        for (int i = 0; i < LL / 8; i++) {
            const float4 vA = p4[2 * i];
            const float4 vB = p4[2 * i + 1];
            a0 += vA.x * Ecol[8 * i + 0];
            a1 += vA.y * Ecol[8 * i + 1];
            a2 += vA.z * Ecol[8 * i + 2];
            a3 += vA.w * Ecol[8 * i + 3];
            a4 += vB.x * Ecol[8 * i + 4];
            a5 += vB.y * Ecol[8 * i + 5];
            a6 += vB.z * Ecol[8 * i + 6];
            a7 += vB.w * Ecol[8 * i + 7];
        }
        const float dot = ((a0 + a1) + (a2 + a3)) + ((a4 + a5) + (a6 + a7));

        const float2 me  = sm_me[g][t];
        const float  nxt = S + __logf(dot) + em_cur;
        s = me.x * nxt + (1.0f - me.x) * s + me.y * et;

        S = sm_s0[buf][g];
    }

    // normalizer = logsumexp_j(s) per batch
    float wm = s;
    #pragma unroll
    for (int o = 16; o; o >>= 1) wm = fmaxf(wm, __shfl_xor_sync(0xffffffffu, wm, o));
    if (lane == 0) sm_red[g][half] = wm;
    __syncthreads();
    const float M = fmaxf(sm_red[g][0], sm_red[g][1]);
    float pe = __expf(s - M);
    #pragma unroll
    for (int o = 16; o; o >>= 1) pe += __shfl_xor_sync(0xffffffffu, pe, o);
    __syncthreads();                                 // sm_red reuse fence
    if (lane == 0) sm_red[g][half] = pe;
    __syncthreads();

    // ---------------- fused deterministic finalization ----------------
    if (j == 0) {
        const float norm = M + __logf(sm_red[g][0] + sm_red[g][1]);
        g_res[b] = norm - path_score;
        __threadfence();                             // publish this write
    }
    __syncthreads();
    if (tid == 0) sm_last = atomicAdd(&g_done, 1u);  // NCTA-1 for last CTA
    __syncthreads();

    if (sm_last == NCTA - 1) {
        __threadfence();                             // acquire all g_res
        float acc = g_res[tid] + g_res[tid + 256];
        #pragma unroll
        for (int o = 16; o; o >>= 1) acc += __shfl_xor_sync(0xffffffffu, acc, o);
        if (lane == 0) sm_fin[tid >> 5] = acc;
        __syncthreads();
        if (tid == 0) {
            float tot = 0.0f;
            #pragma unroll
            for (int w = 0; w < 8; w++) tot += sm_fin[w];
            out[0] = tot * (1.0f / BB);
            g_done = 0;                              // reset for graph replay
        }
    }
}

extern "C" void kernel_launch(void* const* d_in, const int* in_sizes, int n_in,
                              void* d_out, int out_size) {
    const float* emission    = (const float*)d_in[0];
    const int*   target      = (const int*)  d_in[1];
    const float* mask        = (const float*)d_in[2];
    const float* start_trans = (const float*)d_in[3];
    const float* trans       = (const float*)d_in[4];
    const float* end_trans   = (const float*)d_in[5];
    float* out = (float*)d_out;

    crf_main_kernel<<<NCTA, NTHR>>>(emission, target, mask, start_trans, trans,
                                    end_trans, out);
}